// round 16
// baseline (speedup 1.0000x reference)
#include <cuda_runtime.h>
#include <cuda_fp16.h>
#include <math.h>
#include <stdint.h>

#define BATCH 4096
#define LEN   8192
#define NF    2112
#define MIDD  264
#define PP    88
#define NW    (2 * NF)
#define MPAD  384

#define WSCALE    8192.0f
#define ALPHA_INV (1.0f / 8192.0f)
#define TSCALE    64.0f

// ---------------------------------------------------------------------------
// Device scratch
// ---------------------------------------------------------------------------
__device__ float g_scale2[BATCH];
__device__ float g_F  [BATCH * MIDD];          // F' = 2^13 * feat@T
__device__ float g_Y  [BATCH * MIDD];          // Y' = 2^13 * y
__device__ float g_Gf [3 * MPAD * MIDD];       // G partial sums (per K-partition)

__device__ __align__(16) __half g_xhi[(size_t)BATCH * LEN];
__device__ __align__(16) __half g_whi[(size_t)NW * LEN];       // W*2^13
__device__ __align__(16) __half g_fhi [(size_t)BATCH * NF];    // feat' (reused as h2 later)
__device__ __align__(16) __half g_mA  [(size_t)BATCH * MIDD];  // m' ping
__device__ __align__(16) __half g_mB  [(size_t)BATCH * MIDD];  // m' pong / h1
__device__ __align__(16) __half g_tthi[(size_t)MPAD * NF];     // 64*T^T (rows>=264 zero)
__device__ __align__(16) __half g_G   [(size_t)MPAD * MIDD];   // G' = 64*T^T T
__device__ __align__(16) __half g_w1h [MIDD * MIDD];
__device__ __align__(16) __half g_w2h [PP * MIDD];
__device__ __align__(16) __half g_woh [PP * PP];

// ---------------------------------------------------------------------------
// PTX helpers
// ---------------------------------------------------------------------------
__device__ __forceinline__ uint32_t smem_u32(const void* p) {
    uint32_t a;
    asm("{ .reg .u64 t; cvta.to.shared.u64 t, %1; cvt.u32.u64 %0, t; }" : "=r"(a) : "l"(p));
    return a;
}
__device__ __forceinline__ void cp16(uint32_t saddr, const void* gaddr) {
    asm volatile("cp.async.cg.shared.global [%0], [%1], 16;" :: "r"(saddr), "l"(gaddr));
}
__device__ __forceinline__ void cp16z(uint32_t saddr, const void* gaddr, int valid) {
    asm volatile("cp.async.cg.shared.global [%0], [%1], 16, %2;"
                 :: "r"(saddr), "l"(gaddr), "r"(valid ? 16 : 0));
}
__device__ __forceinline__ void cp_commit() { asm volatile("cp.async.commit_group;"); }
__device__ __forceinline__ void cp_wait1()  { asm volatile("cp.async.wait_group 1;" ::: "memory"); }
__device__ __forceinline__ void cp_wait0()  { asm volatile("cp.async.wait_group 0;" ::: "memory"); }

__device__ __forceinline__ void ldsm4(uint32_t r[4], uint32_t a) {
    asm volatile("ldmatrix.sync.aligned.m8n8.x4.shared.b16 {%0,%1,%2,%3}, [%4];"
                 : "=r"(r[0]), "=r"(r[1]), "=r"(r[2]), "=r"(r[3]) : "r"(a));
}
__device__ __forceinline__ void mma16816(float c[4], const uint32_t a[4],
                                         uint32_t b0, uint32_t b1) {
    asm volatile(
        "mma.sync.aligned.m16n8k16.row.col.f32.f16.f16.f32 "
        "{%0,%1,%2,%3}, {%4,%5,%6,%7}, {%8,%9}, {%0,%1,%2,%3};"
        : "+f"(c[0]), "+f"(c[1]), "+f"(c[2]), "+f"(c[3])
        : "r"(a[0]), "r"(a[1]), "r"(a[2]), "r"(a[3]), "r"(b0), "r"(b1));
}

__device__ __forceinline__ uint2 pack4h(float4 v)
{
    uint32_t hb[4];
    float f[4] = {v.x, v.y, v.z, v.w};
    #pragma unroll
    for (int j = 0; j < 4; j++)
        hb[j] = (uint32_t)__half_as_ushort(__float2half_rn(f[j]));
    return make_uint2(hb[0] | (hb[1] << 16), hb[2] | (hb[3] << 16));
}

// ---------------------------------------------------------------------------
// preprocessing kernels
// ---------------------------------------------------------------------------
__global__ void splitcount_x_kernel(const float* __restrict__ x)
{
    int b = blockIdx.x;
    const float4* row = (const float4*)(x + (size_t)b * LEN);
    uint2* oh = (uint2*)(g_xhi + (size_t)b * LEN);
    int cnt = 0;
    for (int i = threadIdx.x; i < LEN / 4; i += 256) {
        float4 v = row[i];
        cnt += (v.x != 0.0f) + (v.y != 0.0f) + (v.z != 0.0f) + (v.w != 0.0f);
        oh[i] = pack4h(v);
    }
    #pragma unroll
    for (int o = 16; o > 0; o >>= 1) cnt += __shfl_down_sync(0xffffffffu, cnt, o);
    __shared__ int ws[8];
    if ((threadIdx.x & 31) == 0) ws[threadIdx.x >> 5] = cnt;
    __syncthreads();
    if (threadIdx.x == 0) {
        int t = 0;
        #pragma unroll
        for (int i = 0; i < 8; i++) t += ws[i];
        float s = (float)LEN / (float)(t + 1);
        g_scale2[b] = s * s * ALPHA_INV;
    }
}

__global__ void split_w_kernel(const float* __restrict__ wc, const float* __restrict__ ws)
{
    int i = blockIdx.x * blockDim.x + threadIdx.x;
    if (i >= NF * (LEN / 4)) return;
    int f  = i / (LEN / 4);
    int kq = i % (LEN / 4);
    float4 vc = ((const float4*)wc)[i];
    vc.x *= WSCALE; vc.y *= WSCALE; vc.z *= WSCALE; vc.w *= WSCALE;
    ((uint2*)g_whi)[(size_t)(2 * f) * (LEN / 4) + kq] = pack4h(vc);
    float4 vs = ((const float4*)ws)[i];
    vs.x *= WSCALE; vs.y *= WSCALE; vs.z *= WSCALE; vs.w *= WSCALE;
    ((uint2*)g_whi)[(size_t)(2 * f + 1) * (LEN / 4) + kq] = pack4h(vs);
}

__global__ void split_t_kernel(const float* __restrict__ tmpl)
{
    int i = blockIdx.x * blockDim.x + threadIdx.x;
    if (i >= NF * MIDD) return;
    int r = i / MIDD, c = i % MIDD;
    g_tthi[(size_t)c * NF + r] = __float2half_rn(tmpl[i] * TSCALE);
}

// tail weights -> fp16 (W1, W2, Wout concatenated)
__global__ void conv_tailw_kernel(const float* __restrict__ W1,
                                  const float* __restrict__ W2,
                                  const float* __restrict__ Wout)
{
    int i = blockIdx.x * blockDim.x + threadIdx.x;
    const int n1 = MIDD * MIDD;
    const int n2 = PP * MIDD;
    const int n3 = PP * PP;
    if (i < n1) g_w1h[i] = __float2half_rn(W1[i]);
    else if (i < n1 + n2) g_w2h[i - n1] = __float2half_rn(W2[i - n1]);
    else if (i < n1 + n2 + n3) g_woh[i - n1 - n2] = __float2half_rn(Wout[i - n1 - n2]);
}

// sum 3 G partials -> fp16 G'
__global__ void gconv_kernel()
{
    int i = blockIdx.x * blockDim.x + threadIdx.x;
    if (i >= MPAD * MIDD) return;
    float s = g_Gf[i] + g_Gf[i + MPAD * MIDD] + g_Gf[i + 2 * MPAD * MIDD];
    g_G[i] = __float2half_rn(s * (1.0f / 64.0f));
}

// ---------------------------------------------------------------------------
// Fourier HMMA: CTA 128x256, 512 threads, 16 warps (64x32 each), KC=64
// ---------------------------------------------------------------------------
#define KC       64
#define FTILE_A  16384                    // 128 rows * 128B
#define FTILE_B  32768                    // 256 rows * 128B
#define STAGE_F  (FTILE_A + FTILE_B)      // 49152
#define FSMEM    (2 * STAGE_F)            // 98304

__device__ __forceinline__ void load_chunk_f(uint32_t sbase, int m0, int n0, int k0, int tid)
{
    const __half* A = g_xhi + (size_t)m0 * LEN;
    #pragma unroll
    for (int j = 0; j < 2; j++) {
        int c  = tid + j * 512;           // 1024 chunks
        int r  = c >> 3;
        int kc = c & 7;
        uint32_t s = sbase + r * 128 + (((uint32_t)(kc ^ (r & 7))) << 4);
        cp16(s, A + (size_t)r * LEN + k0 + kc * 8);
    }
    #pragma unroll
    for (int j = 0; j < 4; j++) {
        int c  = tid + j * 512;           // 2048 chunks
        int r  = c >> 3;                  // 0..255
        int kc = c & 7;
        int nv = (n0 + r < NW);
        uint32_t s = sbase + FTILE_A + r * 128 + (((uint32_t)(kc ^ (r & 7))) << 4);
        const void* g = nv ? (const void*)(g_whi + (size_t)(n0 + r) * LEN + k0 + kc * 8)
                           : (const void*)g_whi;
        cp16z(s, g, nv);
    }
}

__global__ __launch_bounds__(512, 1) void fourier_hmma_kernel()
{
    extern __shared__ char smem_raw[];
    const uint32_t sb = smem_u32(smem_raw);

    const int tid  = threadIdx.x;
    const int wid  = tid >> 5;
    const int lane = tid & 31;
    const int wm   = wid >> 3;            // 0..1 -> 64 rows
    const int wn   = wid & 7;             // 0..7 -> 32 cols

    const int TN = (NW + 255) / 256;      // 17
    const int G  = 8;
    int lin   = blockIdx.y * gridDim.x + blockIdx.x;
    int group = lin / (G * TN);
    int rem   = lin % (G * TN);
    int mt    = group * G + (rem % G);
    int nt    = rem / G;
    const int m0 = mt * 128;
    const int n0 = nt * 256;

    float acc[4][4][4];
    #pragma unroll
    for (int i = 0; i < 4; i++)
        #pragma unroll
        for (int j = 0; j < 4; j++)
            #pragma unroll
            for (int q = 0; q < 4; q++) acc[i][j][q] = 0.0f;

    const int a_r   = lane & 15;
    const int a_k8  = lane >> 4;
    const uint32_t a_x = (uint32_t)(a_r & 7);
    const int bg    = lane >> 3;
    const int b_n   = ((bg >> 1) << 3) + (lane & 7);
    const int b_k8  = bg & 1;
    const uint32_t b_x = (uint32_t)(lane & 7);

    uint32_t a_row_b[4], b_row_b[2];
    #pragma unroll
    for (int mi = 0; mi < 4; mi++) a_row_b[mi] = (uint32_t)(wm * 64 + mi * 16 + a_r) * 128u;
    #pragma unroll
    for (int pr = 0; pr < 2; pr++) b_row_b[pr] = (uint32_t)(wn * 32 + pr * 16 + b_n) * 128u;

    const int NCH = LEN / KC;
    load_chunk_f(sb, m0, n0, 0, tid);
    cp_commit();

    for (int i = 0; i < NCH; i++) {
        const uint32_t su = sb + (uint32_t)(i & 1) * STAGE_F;
        if (i + 1 < NCH) {
            load_chunk_f(sb + (uint32_t)((i + 1) & 1) * STAGE_F, m0, n0, (i + 1) * KC, tid);
            cp_commit();
            cp_wait1();
        } else {
            cp_wait0();
        }
        __syncthreads();

        const uint32_t ah_b = su;
        const uint32_t bh_b = su + FTILE_A;

        #pragma unroll
        for (int ks = 0; ks < KC / 16; ks++) {
            const uint32_t akc = (uint32_t)(ks * 2 + a_k8);
            const uint32_t bkc = (uint32_t)(ks * 2 + b_k8);
            uint32_t ah[4][4];
            #pragma unroll
            for (int mi = 0; mi < 4; mi++)
                ldsm4(ah[mi], ah_b + a_row_b[mi] + ((akc ^ a_x) << 4));
            uint32_t bh[8];
            #pragma unroll
            for (int pr = 0; pr < 2; pr++)
                ldsm4(&bh[pr * 4], bh_b + b_row_b[pr] + ((bkc ^ b_x) << 4));
            #pragma unroll
            for (int mi = 0; mi < 4; mi++)
                #pragma unroll
                for (int ni = 0; ni < 4; ni++)
                    mma16816(acc[mi][ni], ah[mi], bh[ni * 2], bh[ni * 2 + 1]);
        }
        __syncthreads();
    }

    // epilogue: feat' = s2 * (c^2 + s^2)
    const int qr = lane >> 2;
    const int qc = lane & 3;
    const int fbase = (n0 >> 1) + wn * 16;
    #pragma unroll
    for (int mi = 0; mi < 4; mi++) {
        int row0 = m0 + wm * 64 + mi * 16 + qr;
        int row1 = row0 + 8;
        float s20 = g_scale2[row0];
        float s21 = g_scale2[row1];
        size_t b0 = (size_t)row0 * NF;
        size_t b1 = (size_t)row1 * NF;
        #pragma unroll
        for (int ni = 0; ni < 4; ni++) {
            int f = fbase + ni * 4 + qc;
            if (f < NF) {
                float c0 = acc[mi][ni][0], c1 = acc[mi][ni][1];
                float c2 = acc[mi][ni][2], c3 = acc[mi][ni][3];
                g_fhi[b0 + f] = __float2half_rn(s20 * (c0 * c0 + c1 * c1));
                g_fhi[b1 + f] = __float2half_rn(s21 * (c2 * c2 + c3 * c3));
            }
        }
    }
}

// ---------------------------------------------------------------------------
// LISTA-family HMMA: CTA 128x64, KC=64, single-pass fp16
// EPI 1 (F):   Cf = acc/64 (=F'), Chi = relu((10/64)*acc) (=m0')
// EPI 3 (IT):  vy = (1.6/64)*acc + c0*Fp + c1*Yp ; Yp = vy
//              Chi = relu(-8*vy + 0.2*Min)
// EPI 4 (relu+bias):    Chi = fp16(relu(c0*acc + Fp[col]))
// EPI 6 (sigmoid+bias): Cf  = sigmoid(acc + Fp[col])
// EPI 7 (G partial):    Cf[z*MPAD*MIDD + idx] = acc
// ---------------------------------------------------------------------------
#define TILE_A   16384
#define TILE_Bs  8192
#define LSTAGE   (TILE_A + TILE_Bs)
#define LSMEM    (2 * LSTAGE)

__device__ __forceinline__ void load_chunk_l(
    uint32_t sbase,
    const __half* __restrict__ Ahi, int lda, int m0,
    const __half* __restrict__ Bhi, int ldb, int n0, int N,
    int k0, int kend, int tid)
{
    #pragma unroll
    for (int j = 0; j < 4; j++) {
        int c  = tid + j * 256;
        int r  = c >> 3;
        int kc = c & 7;
        int k  = k0 + kc * 8;
        int kv = (k < kend);
        uint32_t soff = (uint32_t)r * 128u + (((uint32_t)(kc ^ (r & 7))) << 4);
        cp16z(sbase + soff,
              kv ? (const void*)(Ahi + (size_t)(m0 + r) * lda + k) : (const void*)Ahi, kv);
    }
    #pragma unroll
    for (int j = 0; j < 2; j++) {
        int c  = tid + j * 256;
        int r  = c >> 3;
        int kc = c & 7;
        int k  = k0 + kc * 8;
        int nv = (k < kend) && (n0 + r < N);
        uint32_t soff = (uint32_t)r * 128u + (((uint32_t)(kc ^ (r & 7))) << 4);
        cp16z(sbase + TILE_A + soff,
              nv ? (const void*)(Bhi + (size_t)(n0 + r) * ldb + k) : (const void*)Bhi, nv);
    }
}

template<int EPI>
__global__ __launch_bounds__(256, 2) void lista_hmma_kernel(
    const __half* __restrict__ Ahi, int lda,
    const __half* __restrict__ Bhi, int ldb,
    int N, int K, int kstep,
    __half* __restrict__ Chi, float* __restrict__ Cf, int ldc,
    const float* __restrict__ Fp, float* __restrict__ Yp,
    const __half* __restrict__ Min,
    float c0, float c1)
{
    extern __shared__ char smem_raw[];
    const uint32_t sb = smem_u32(smem_raw);

    const int tid  = threadIdx.x;
    const int wid  = tid >> 5;
    const int lane = tid & 31;
    const int wm   = wid >> 1;
    const int wn   = wid & 1;
    const int m0   = blockIdx.y * 128;
    const int n0   = blockIdx.x * 64;
    const int kbeg = blockIdx.z * kstep;
    const int kend = (kbeg + kstep < K) ? (kbeg + kstep) : K;

    float acc[2][4][4];
    #pragma unroll
    for (int i = 0; i < 2; i++)
        #pragma unroll
        for (int j = 0; j < 4; j++)
            #pragma unroll
            for (int q = 0; q < 4; q++) acc[i][j][q] = 0.0f;

    const int a_r   = lane & 15;
    const int a_k8  = lane >> 4;
    const uint32_t a_x = (uint32_t)(a_r & 7);
    const int bg    = lane >> 3;
    const int b_n   = ((bg >> 1) << 3) + (lane & 7);
    const int b_k8  = bg & 1;
    const uint32_t b_x = (uint32_t)(lane & 7);

    uint32_t a_row_b[2], b_row_b[2];
    #pragma unroll
    for (int mi = 0; mi < 2; mi++) a_row_b[mi] = (uint32_t)(wm * 32 + mi * 16 + a_r) * 128u;
    #pragma unroll
    for (int pr = 0; pr < 2; pr++) b_row_b[pr] = (uint32_t)(wn * 32 + pr * 16 + b_n) * 128u;

    const int NCH = (kend - kbeg + KC - 1) / KC;
    load_chunk_l(sb, Ahi, lda, m0, Bhi, ldb, n0, N, kbeg, kend, tid);
    cp_commit();

    for (int i = 0; i < NCH; i++) {
        const uint32_t su = sb + (uint32_t)(i & 1) * LSTAGE;
        if (i + 1 < NCH) {
            load_chunk_l(sb + (uint32_t)((i + 1) & 1) * LSTAGE,
                         Ahi, lda, m0, Bhi, ldb, n0, N, kbeg + (i + 1) * KC, kend, tid);
            cp_commit();
            cp_wait1();
        } else {
            cp_wait0();
        }
        __syncthreads();

        const uint32_t ah_b = su;
        const uint32_t bh_b = su + TILE_A;

        #pragma unroll
        for (int ks = 0; ks < KC / 16; ks++) {
            const uint32_t akc = (uint32_t)(ks * 2 + a_k8);
            const uint32_t bkc = (uint32_t)(ks * 2 + b_k8);
            uint32_t ah[2][4];
            #pragma unroll
            for (int mi = 0; mi < 2; mi++)
                ldsm4(ah[mi], ah_b + a_row_b[mi] + ((akc ^ a_x) << 4));
            uint32_t bh[8];
            #pragma unroll
            for (int pr = 0; pr < 2; pr++)
                ldsm4(&bh[pr * 4], bh_b + b_row_b[pr] + ((bkc ^ b_x) << 4));
            #pragma unroll
            for (int mi = 0; mi < 2; mi++)
                #pragma unroll
                for (int ni = 0; ni < 4; ni++)
                    mma16816(acc[mi][ni], ah[mi], bh[ni * 2], bh[ni * 2 + 1]);
        }
        __syncthreads();
    }

    const int qr = lane >> 2;
    const int qc = lane & 3;
    #pragma unroll
    for (int mi = 0; mi < 2; mi++) {
        int rows[2];
        rows[0] = m0 + wm * 32 + mi * 16 + qr;
        rows[1] = rows[0] + 8;
        #pragma unroll
        for (int ni = 0; ni < 4; ni++) {
            int colb = n0 + wn * 32 + ni * 8 + qc * 2;
            #pragma unroll
            for (int h = 0; h < 2; h++) {
                #pragma unroll
                for (int cc = 0; cc < 2; cc++) {
                    int col = colb + cc;
                    if (col >= N) continue;
                    size_t idx = (size_t)rows[h] * ldc + col;
                    float a = acc[mi][ni][h * 2 + cc];
                    if (EPI == 1) {
                        Cf[idx] = a * (1.0f / 64.0f);
                        Chi[idx] = __float2half_rn(fmaxf((10.0f / 64.0f) * a, 0.0f));
                    } else if (EPI == 3) {
                        float vy = (1.6f / 64.0f) * a + c0 * Fp[idx];
                        if (c1 != 0.0f) vy += c1 * Yp[idx];
                        Yp[idx] = vy;
                        float vm = fmaxf(-8.0f * vy + 0.2f * __half2float(Min[idx]), 0.0f);
                        Chi[idx] = __float2half_rn(vm);
                    } else if (EPI == 4) {
                        Chi[idx] = __float2half_rn(fmaxf(c0 * a + Fp[col], 0.0f));
                    } else if (EPI == 6) {
                        float z = a + Fp[col];
                        Cf[idx] = 1.0f / (1.0f + expf(-z));
                    } else {  // EPI 7
                        Cf[(size_t)blockIdx.z * (MPAD * MIDD) + idx] = a;
                    }
                }
            }
        }
    }
}

// ---------------------------------------------------------------------------
extern "C" void kernel_launch(void* const* d_in, const int* in_sizes, int n_in,
                              void* d_out, int out_size)
{
    const float* input_this = (const float*)d_in[0];
    const float* W_cos = (const float*)d_in[2];
    const float* W_sin = (const float*)d_in[3];
    const float* tmpl  = (const float*)d_in[4];
    const float* W1    = (const float*)d_in[5];
    const float* b1    = (const float*)d_in[6];
    const float* W2    = (const float*)d_in[7];
    const float* b2    = (const float*)d_in[8];
    const float* Wout  = (const float*)d_in[9];
    const float* bout  = (const float*)d_in[10];
    float* out = (float*)d_out;

    float *p_F, *p_Y, *p_Gf;
    cudaGetSymbolAddress((void**)&p_F,  g_F);
    cudaGetSymbolAddress((void**)&p_Y,  g_Y);
    cudaGetSymbolAddress((void**)&p_Gf, g_Gf);
    __half *p_fhi, *p_mA, *p_mB, *p_tthi, *p_G, *p_w1h, *p_w2h, *p_woh;
    cudaGetSymbolAddress((void**)&p_fhi,  g_fhi);
    cudaGetSymbolAddress((void**)&p_mA,   g_mA);
    cudaGetSymbolAddress((void**)&p_mB,   g_mB);
    cudaGetSymbolAddress((void**)&p_tthi, g_tthi);
    cudaGetSymbolAddress((void**)&p_G,    g_G);
    cudaGetSymbolAddress((void**)&p_w1h,  g_w1h);
    cudaGetSymbolAddress((void**)&p_w2h,  g_w2h);
    cudaGetSymbolAddress((void**)&p_woh,  g_woh);

    dim3 blk(256);

    splitcount_x_kernel<<<BATCH, blk>>>(input_this);
    split_w_kernel<<<(NF * LEN / 4 + 255) / 256, blk>>>(W_cos, W_sin);
    split_t_kernel<<<(NF * MIDD + 255) / 256, blk>>>(tmpl);
    conv_tailw_kernel<<<(MIDD * MIDD + PP * MIDD + PP * PP + 255) / 256, blk>>>(W1, W2, Wout);

    cudaFuncSetAttribute(fourier_hmma_kernel,
                         cudaFuncAttributeMaxDynamicSharedMemorySize, FSMEM);
    cudaFuncSetAttribute(lista_hmma_kernel<1>,
                         cudaFuncAttributeMaxDynamicSharedMemorySize, LSMEM);
    cudaFuncSetAttribute(lista_hmma_kernel<3>,
                         cudaFuncAttributeMaxDynamicSharedMemorySize, LSMEM);
    cudaFuncSetAttribute(lista_hmma_kernel<4>,
                         cudaFuncAttributeMaxDynamicSharedMemorySize, LSMEM);
    cudaFuncSetAttribute(lista_hmma_kernel<6>,
                         cudaFuncAttributeMaxDynamicSharedMemorySize, LSMEM);
    cudaFuncSetAttribute(lista_hmma_kernel<7>,
                         cudaFuncAttributeMaxDynamicSharedMemorySize, LSMEM);

    // G partials: K=2112 split 3x704 (grid.z), each partition to its own buffer
    lista_hmma_kernel<7><<<dim3((MIDD + 63) / 64, MPAD / 128, 3), blk, LSMEM>>>(
        p_tthi, NF, p_tthi, NF, MIDD, NF, 704,
        nullptr, p_Gf, MIDD, nullptr, nullptr, nullptr, 0.f, 0.f);
    gconv_kernel<<<(MPAD * MIDD + 255) / 256, blk>>>();

    // Fourier (128x256 tiles, 512 threads)
    fourier_hmma_kernel<<<dim3((NW + 255) / 256, BATCH / 128), dim3(512), FSMEM>>>();

    dim3 gMID((MIDD + 63) / 64, BATCH / 128);   // 5 x 32

    // F' = 2^13 feat@T ; m0' = relu(10F)*2^13
    lista_hmma_kernel<1><<<gMID, blk, LSMEM>>>(
        p_fhi, NF, p_tthi, NF, MIDD, NF, NF,
        p_mA, p_F, MIDD, nullptr, nullptr, nullptr, 0.f, 0.f);

    // 4 fused iterations on [4096x264]@[264x264]; final m' lands in g_mA
    __half* mi = p_mA;
    __half* mo = p_mB;
    for (int it = 0; it < 4; it++) {
        float c0 = (it == 0) ? -1.8f : -1.6f;
        float c1 = (it == 0) ?  0.0f :  0.2f;
        lista_hmma_kernel<3><<<gMID, blk, LSMEM>>>(
            mi, MIDD, p_G, MIDD, MIDD, MIDD, MIDD,
            mo, nullptr, MIDD, p_F, p_Y, mi, c0, c1);
        __half* tmp = mi; mi = mo; mo = tmp;
    }
    // after 4 swaps, mi == p_mA (final m' = 2^13*m)

    // h1 = relu(2^-13 * m'@W1^T + b1) -> g_mB (fp16)
    lista_hmma_kernel<4><<<gMID, blk, LSMEM>>>(
        p_mA, MIDD, p_w1h, MIDD, MIDD, MIDD, MIDD,
        p_mB, nullptr, MIDD, b1, nullptr, nullptr, ALPHA_INV, 0.f);

    // h2 = relu(h1@W2^T + b2) -> g_fhi reused (fp16)
    lista_hmma_kernel<4><<<dim3((PP + 63) / 64, BATCH / 128), blk, LSMEM>>>(
        p_mB, MIDD, p_w2h, MIDD, PP, MIDD, MIDD,
        p_fhi, nullptr, PP, b2, nullptr, nullptr, 1.0f, 0.f);

    // out = sigmoid(h2@Wout^T + bout) -> fp32 d_out
    lista_hmma_kernel<6><<<dim3((PP + 63) / 64, BATCH / 128), blk, LSMEM>>>(
        p_fhi, PP, p_woh, PP, PP, PP, PP,
        nullptr, out, PP, bout, nullptr, nullptr, 0.f, 0.f);
}

// round 17
// speedup vs baseline: 1.1807x; 1.1807x over previous
#include <cuda_runtime.h>
#include <cuda_fp16.h>
#include <math.h>
#include <stdint.h>

#define BATCH 4096
#define LEN   8192
#define NF    2112
#define MIDD  264
#define PP    88
#define NW    (2 * NF)
#define MPAD  384

#define WSCALE    8192.0f
#define ALPHA_INV (1.0f / 8192.0f)
#define TSCALE    64.0f

// ---------------------------------------------------------------------------
// Device scratch
// ---------------------------------------------------------------------------
__device__ float g_scale2[BATCH];
__device__ float g_F  [BATCH * MIDD];          // F' = 2^13 * feat@T
__device__ float g_Y  [BATCH * MIDD];          // Y' = 2^13 * y
__device__ float g_Gf [3 * MPAD * MIDD];       // G partial sums

__device__ __align__(16) __half g_xhi[(size_t)BATCH * LEN];
__device__ __align__(16) __half g_whi[(size_t)NW * LEN];       // W*2^13
__device__ __align__(16) __half g_fhi [(size_t)BATCH * NF];    // feat' (reused as h2)
__device__ __align__(16) __half g_mA  [(size_t)BATCH * MIDD];
__device__ __align__(16) __half g_mB  [(size_t)BATCH * MIDD];
__device__ __align__(16) __half g_tthi[(size_t)MPAD * NF];     // 64*T^T (rows>=264 zero)
__device__ __align__(16) __half g_G   [(size_t)MPAD * MIDD];   // G' = 64*T^T T
__device__ __align__(16) __half g_w1h [MIDD * MIDD];
__device__ __align__(16) __half g_w2h [PP * MIDD];
__device__ __align__(16) __half g_woh [PP * PP];

// ---------------------------------------------------------------------------
// PTX helpers
// ---------------------------------------------------------------------------
__device__ __forceinline__ uint32_t smem_u32(const void* p) {
    uint32_t a;
    asm("{ .reg .u64 t; cvta.to.shared.u64 t, %1; cvt.u32.u64 %0, t; }" : "=r"(a) : "l"(p));
    return a;
}
__device__ __forceinline__ void cp16(uint32_t saddr, const void* gaddr) {
    asm volatile("cp.async.cg.shared.global [%0], [%1], 16;" :: "r"(saddr), "l"(gaddr));
}
__device__ __forceinline__ void cp16z(uint32_t saddr, const void* gaddr, int valid) {
    asm volatile("cp.async.cg.shared.global [%0], [%1], 16, %2;"
                 :: "r"(saddr), "l"(gaddr), "r"(valid ? 16 : 0));
}
__device__ __forceinline__ void cp_commit() { asm volatile("cp.async.commit_group;"); }
__device__ __forceinline__ void cp_wait1()  { asm volatile("cp.async.wait_group 1;" ::: "memory"); }
__device__ __forceinline__ void cp_wait0()  { asm volatile("cp.async.wait_group 0;" ::: "memory"); }

__device__ __forceinline__ void ldsm4(uint32_t r[4], uint32_t a) {
    asm volatile("ldmatrix.sync.aligned.m8n8.x4.shared.b16 {%0,%1,%2,%3}, [%4];"
                 : "=r"(r[0]), "=r"(r[1]), "=r"(r[2]), "=r"(r[3]) : "r"(a));
}
__device__ __forceinline__ void mma16816(float c[4], const uint32_t a[4],
                                         uint32_t b0, uint32_t b1) {
    asm volatile(
        "mma.sync.aligned.m16n8k16.row.col.f32.f16.f16.f32 "
        "{%0,%1,%2,%3}, {%4,%5,%6,%7}, {%8,%9}, {%0,%1,%2,%3};"
        : "+f"(c[0]), "+f"(c[1]), "+f"(c[2]), "+f"(c[3])
        : "r"(a[0]), "r"(a[1]), "r"(a[2]), "r"(a[3]), "r"(b0), "r"(b1));
}

__device__ __forceinline__ uint2 pack4h(float4 v)
{
    uint32_t hb[4];
    float f[4] = {v.x, v.y, v.z, v.w};
    #pragma unroll
    for (int j = 0; j < 4; j++)
        hb[j] = (uint32_t)__half_as_ushort(__float2half_rn(f[j]));
    return make_uint2(hb[0] | (hb[1] << 16), hb[2] | (hb[3] << 16));
}

// ---------------------------------------------------------------------------
// preprocessing kernels
// ---------------------------------------------------------------------------
__global__ void splitcount_x_kernel(const float* __restrict__ x)
{
    int b = blockIdx.x;
    const float4* row = (const float4*)(x + (size_t)b * LEN);
    uint2* oh = (uint2*)(g_xhi + (size_t)b * LEN);
    int cnt = 0;
    for (int i = threadIdx.x; i < LEN / 4; i += 256) {
        float4 v = row[i];
        cnt += (v.x != 0.0f) + (v.y != 0.0f) + (v.z != 0.0f) + (v.w != 0.0f);
        oh[i] = pack4h(v);
    }
    #pragma unroll
    for (int o = 16; o > 0; o >>= 1) cnt += __shfl_down_sync(0xffffffffu, cnt, o);
    __shared__ int ws[8];
    if ((threadIdx.x & 31) == 0) ws[threadIdx.x >> 5] = cnt;
    __syncthreads();
    if (threadIdx.x == 0) {
        int t = 0;
        #pragma unroll
        for (int i = 0; i < 8; i++) t += ws[i];
        float s = (float)LEN / (float)(t + 1);
        g_scale2[b] = s * s * ALPHA_INV;
    }
}

__global__ void split_w_kernel(const float* __restrict__ wc, const float* __restrict__ ws)
{
    int i = blockIdx.x * blockDim.x + threadIdx.x;
    if (i >= NF * (LEN / 4)) return;
    int f  = i / (LEN / 4);
    int kq = i % (LEN / 4);
    float4 vc = ((const float4*)wc)[i];
    vc.x *= WSCALE; vc.y *= WSCALE; vc.z *= WSCALE; vc.w *= WSCALE;
    ((uint2*)g_whi)[(size_t)(2 * f) * (LEN / 4) + kq] = pack4h(vc);
    float4 vs = ((const float4*)ws)[i];
    vs.x *= WSCALE; vs.y *= WSCALE; vs.z *= WSCALE; vs.w *= WSCALE;
    ((uint2*)g_whi)[(size_t)(2 * f + 1) * (LEN / 4) + kq] = pack4h(vs);
}

__global__ void split_t_kernel(const float* __restrict__ tmpl)
{
    int i = blockIdx.x * blockDim.x + threadIdx.x;
    if (i >= NF * MIDD) return;
    int r = i / MIDD, c = i % MIDD;
    g_tthi[(size_t)c * NF + r] = __float2half_rn(tmpl[i] * TSCALE);
}

__global__ void conv_tailw_kernel(const float* __restrict__ W1,
                                  const float* __restrict__ W2,
                                  const float* __restrict__ Wout)
{
    int i = blockIdx.x * blockDim.x + threadIdx.x;
    const int n1 = MIDD * MIDD;
    const int n2 = PP * MIDD;
    const int n3 = PP * PP;
    if (i < n1) g_w1h[i] = __float2half_rn(W1[i]);
    else if (i < n1 + n2) g_w2h[i - n1] = __float2half_rn(W2[i - n1]);
    else if (i < n1 + n2 + n3) g_woh[i - n1 - n2] = __float2half_rn(Wout[i - n1 - n2]);
}

__global__ void gconv_kernel()
{
    int i = blockIdx.x * blockDim.x + threadIdx.x;
    if (i >= MPAD * MIDD) return;
    float s = g_Gf[i] + g_Gf[i + MPAD * MIDD] + g_Gf[i + 2 * MPAD * MIDD];
    g_G[i] = __float2half_rn(s * (1.0f / 64.0f));
}

// ---------------------------------------------------------------------------
// Fourier HMMA: CTA 128x128, 256 threads, KC=64, 2 CTAs/SM  (R15-proven)
// ---------------------------------------------------------------------------
#define KC       64
#define TILE_T   (128 * KC * 2)
#define STAGE_F  (2 * TILE_T)
#define FSMEM    (2 * STAGE_F)           // 65536

__device__ __forceinline__ void load_chunk(uint32_t sbase, int m0, int n0, int k0, int tid)
{
    const __half* srcs[2] = { g_xhi + (size_t)m0 * LEN, g_whi + (size_t)n0 * LEN };
    #pragma unroll
    for (int t = 0; t < 2; t++) {
        uint32_t tb = sbase + t * TILE_T;
        #pragma unroll
        for (int j = 0; j < 4; j++) {
            int c  = tid + j * 256;
            int r  = c >> 3;
            int kc = c & 7;
            const void* g = srcs[t] + (size_t)r * LEN + k0 + kc * 8;
            uint32_t s = tb + r * 128 + (((uint32_t)(kc ^ (r & 7))) << 4);
            cp16(s, g);
        }
    }
}

__global__ __launch_bounds__(256, 2) void fourier_hmma_kernel()
{
    extern __shared__ char smem_raw[];
    const uint32_t sb = smem_u32(smem_raw);

    const int tid  = threadIdx.x;
    const int wid  = tid >> 5;
    const int lane = tid & 31;
    const int wm   = wid >> 2;
    const int wn   = wid & 3;

    const int TN = NW / 128;             // 33
    const int G  = 8;
    int lin   = blockIdx.y * gridDim.x + blockIdx.x;
    int group = lin / (G * TN);
    int rem   = lin % (G * TN);
    int mt    = group * G + (rem % G);
    int nt    = rem / G;
    const int m0 = mt * 128;
    const int n0 = nt * 128;

    float acc[4][4][4];
    #pragma unroll
    for (int i = 0; i < 4; i++)
        #pragma unroll
        for (int j = 0; j < 4; j++)
            #pragma unroll
            for (int q = 0; q < 4; q++) acc[i][j][q] = 0.0f;

    const int a_r   = lane & 15;
    const int a_k8  = lane >> 4;
    const uint32_t a_x = (uint32_t)(a_r & 7);
    const int bg    = lane >> 3;
    const int b_n   = ((bg >> 1) << 3) + (lane & 7);
    const int b_k8  = bg & 1;
    const uint32_t b_x = (uint32_t)(lane & 7);

    uint32_t a_row_b[4], b_row_b[2];
    #pragma unroll
    for (int mi = 0; mi < 4; mi++) a_row_b[mi] = (uint32_t)(wm * 64 + mi * 16 + a_r) * 128u;
    #pragma unroll
    for (int pr = 0; pr < 2; pr++) b_row_b[pr] = (uint32_t)(wn * 32 + pr * 16 + b_n) * 128u;

    const int NCH = LEN / KC;
    load_chunk(sb, m0, n0, 0, tid);
    cp_commit();

    for (int i = 0; i < NCH; i++) {
        const uint32_t su = sb + (uint32_t)(i & 1) * STAGE_F;
        if (i + 1 < NCH) {
            load_chunk(sb + (uint32_t)((i + 1) & 1) * STAGE_F, m0, n0, (i + 1) * KC, tid);
            cp_commit();
            cp_wait1();
        } else {
            cp_wait0();
        }
        __syncthreads();

        const uint32_t ah_b = su;
        const uint32_t bh_b = su + TILE_T;

        #pragma unroll
        for (int ks = 0; ks < KC / 16; ks++) {
            const uint32_t akc = (uint32_t)(ks * 2 + a_k8);
            const uint32_t bkc = (uint32_t)(ks * 2 + b_k8);
            uint32_t ah[4][4];
            #pragma unroll
            for (int mi = 0; mi < 4; mi++)
                ldsm4(ah[mi], ah_b + a_row_b[mi] + ((akc ^ a_x) << 4));
            uint32_t bh[8];
            #pragma unroll
            for (int pr = 0; pr < 2; pr++)
                ldsm4(&bh[pr * 4], bh_b + b_row_b[pr] + ((bkc ^ b_x) << 4));
            #pragma unroll
            for (int mi = 0; mi < 4; mi++)
                #pragma unroll
                for (int ni = 0; ni < 4; ni++)
                    mma16816(acc[mi][ni], ah[mi], bh[ni * 2], bh[ni * 2 + 1]);
        }
        __syncthreads();
    }

    const int qr = lane >> 2;
    const int qc = lane & 3;
    const int fbase = (n0 >> 1) + wn * 16;
    #pragma unroll
    for (int mi = 0; mi < 4; mi++) {
        int row0 = m0 + wm * 64 + mi * 16 + qr;
        int row1 = row0 + 8;
        float s20 = g_scale2[row0];
        float s21 = g_scale2[row1];
        size_t b0 = (size_t)row0 * NF;
        size_t b1 = (size_t)row1 * NF;
        #pragma unroll
        for (int ni = 0; ni < 4; ni++) {
            int f = fbase + ni * 4 + qc;
            float c0 = acc[mi][ni][0], c1 = acc[mi][ni][1];
            float c2 = acc[mi][ni][2], c3 = acc[mi][ni][3];
            g_fhi[b0 + f] = __float2half_rn(s20 * (c0 * c0 + c1 * c1));
            g_fhi[b1 + f] = __float2half_rn(s21 * (c2 * c2 + c3 * c3));
        }
    }
}

// ---------------------------------------------------------------------------
// LISTA-family HMMA: CTA 128x64, KC=64, single-pass fp16
// EPI 1 (F):   Cf = acc/64 (=F'), Chi = relu((10/64)*acc) (=m0')
// EPI 3 (IT):  vy = (1.6/64)*acc + c0*Fp + c1*Yp ; Yp = vy
//              Chi = relu(-8*vy + 0.2*Min)
// EPI 4 (relu+bias):    Chi = fp16(relu(c0*acc + Fp[col]))
// EPI 6 (sigmoid+bias): Cf  = sigmoid(acc + Fp[col])
// EPI 7 (G partial):    Cf[z*MPAD*MIDD + idx] = acc
// ---------------------------------------------------------------------------
#define TILE_A   16384
#define TILE_Bs  8192
#define LSTAGE   (TILE_A + TILE_Bs)
#define LSMEM    (2 * LSTAGE)

__device__ __forceinline__ void load_chunk_l(
    uint32_t sbase,
    const __half* __restrict__ Ahi, int lda, int m0,
    const __half* __restrict__ Bhi, int ldb, int n0, int N,
    int k0, int kend, int tid)
{
    #pragma unroll
    for (int j = 0; j < 4; j++) {
        int c  = tid + j * 256;
        int r  = c >> 3;
        int kc = c & 7;
        int k  = k0 + kc * 8;
        int kv = (k < kend);
        uint32_t soff = (uint32_t)r * 128u + (((uint32_t)(kc ^ (r & 7))) << 4);
        cp16z(sbase + soff,
              kv ? (const void*)(Ahi + (size_t)(m0 + r) * lda + k) : (const void*)Ahi, kv);
    }
    #pragma unroll
    for (int j = 0; j < 2; j++) {
        int c  = tid + j * 256;
        int r  = c >> 3;
        int kc = c & 7;
        int k  = k0 + kc * 8;
        int nv = (k < kend) && (n0 + r < N);
        uint32_t soff = (uint32_t)r * 128u + (((uint32_t)(kc ^ (r & 7))) << 4);
        cp16z(sbase + TILE_A + soff,
              nv ? (const void*)(Bhi + (size_t)(n0 + r) * ldb + k) : (const void*)Bhi, nv);
    }
}

template<int EPI>
__global__ __launch_bounds__(256, 2) void lista_hmma_kernel(
    const __half* __restrict__ Ahi, int lda,
    const __half* __restrict__ Bhi, int ldb,
    int N, int K, int kstep,
    __half* __restrict__ Chi, float* __restrict__ Cf, int ldc,
    const float* __restrict__ Fp, float* __restrict__ Yp,
    const __half* __restrict__ Min,
    float c0, float c1)
{
    extern __shared__ char smem_raw[];
    const uint32_t sb = smem_u32(smem_raw);

    const int tid  = threadIdx.x;
    const int wid  = tid >> 5;
    const int lane = tid & 31;
    const int wm   = wid >> 1;
    const int wn   = wid & 1;
    const int m0   = blockIdx.y * 128;
    const int n0   = blockIdx.x * 64;
    const int kbeg = blockIdx.z * kstep;
    const int kend = (kbeg + kstep < K) ? (kbeg + kstep) : K;

    float acc[2][4][4];
    #pragma unroll
    for (int i = 0; i < 2; i++)
        #pragma unroll
        for (int j = 0; j < 4; j++)
            #pragma unroll
            for (int q = 0; q < 4; q++) acc[i][j][q] = 0.0f;

    const int a_r   = lane & 15;
    const int a_k8  = lane >> 4;
    const uint32_t a_x = (uint32_t)(a_r & 7);
    const int bg    = lane >> 3;
    const int b_n   = ((bg >> 1) << 3) + (lane & 7);
    const int b_k8  = bg & 1;
    const uint32_t b_x = (uint32_t)(lane & 7);

    uint32_t a_row_b[2], b_row_b[2];
    #pragma unroll
    for (int mi = 0; mi < 2; mi++) a_row_b[mi] = (uint32_t)(wm * 32 + mi * 16 + a_r) * 128u;
    #pragma unroll
    for (int pr = 0; pr < 2; pr++) b_row_b[pr] = (uint32_t)(wn * 32 + pr * 16 + b_n) * 128u;

    const int NCH = (kend - kbeg + KC - 1) / KC;
    load_chunk_l(sb, Ahi, lda, m0, Bhi, ldb, n0, N, kbeg, kend, tid);
    cp_commit();

    for (int i = 0; i < NCH; i++) {
        const uint32_t su = sb + (uint32_t)(i & 1) * LSTAGE;
        if (i + 1 < NCH) {
            load_chunk_l(sb + (uint32_t)((i + 1) & 1) * LSTAGE,
                         Ahi, lda, m0, Bhi, ldb, n0, N, kbeg + (i + 1) * KC, kend, tid);
            cp_commit();
            cp_wait1();
        } else {
            cp_wait0();
        }
        __syncthreads();

        const uint32_t ah_b = su;
        const uint32_t bh_b = su + TILE_A;

        #pragma unroll
        for (int ks = 0; ks < KC / 16; ks++) {
            const uint32_t akc = (uint32_t)(ks * 2 + a_k8);
            const uint32_t bkc = (uint32_t)(ks * 2 + b_k8);
            uint32_t ah[2][4];
            #pragma unroll
            for (int mi = 0; mi < 2; mi++)
                ldsm4(ah[mi], ah_b + a_row_b[mi] + ((akc ^ a_x) << 4));
            uint32_t bh[8];
            #pragma unroll
            for (int pr = 0; pr < 2; pr++)
                ldsm4(&bh[pr * 4], bh_b + b_row_b[pr] + ((bkc ^ b_x) << 4));
            #pragma unroll
            for (int mi = 0; mi < 2; mi++)
                #pragma unroll
                for (int ni = 0; ni < 4; ni++)
                    mma16816(acc[mi][ni], ah[mi], bh[ni * 2], bh[ni * 2 + 1]);
        }
        __syncthreads();
    }

    const int qr = lane >> 2;
    const int qc = lane & 3;
    #pragma unroll
    for (int mi = 0; mi < 2; mi++) {
        int rows[2];
        rows[0] = m0 + wm * 32 + mi * 16 + qr;
        rows[1] = rows[0] + 8;
        #pragma unroll
        for (int ni = 0; ni < 4; ni++) {
            int colb = n0 + wn * 32 + ni * 8 + qc * 2;
            #pragma unroll
            for (int h = 0; h < 2; h++) {
                #pragma unroll
                for (int cc = 0; cc < 2; cc++) {
                    int col = colb + cc;
                    if (col >= N) continue;
                    size_t idx = (size_t)rows[h] * ldc + col;
                    float a = acc[mi][ni][h * 2 + cc];
                    if (EPI == 1) {
                        Cf[idx] = a * (1.0f / 64.0f);
                        Chi[idx] = __float2half_rn(fmaxf((10.0f / 64.0f) * a, 0.0f));
                    } else if (EPI == 3) {
                        float vy = (1.6f / 64.0f) * a + c0 * Fp[idx];
                        if (c1 != 0.0f) vy += c1 * Yp[idx];
                        Yp[idx] = vy;
                        float vm = fmaxf(-8.0f * vy + 0.2f * __half2float(Min[idx]), 0.0f);
                        Chi[idx] = __float2half_rn(vm);
                    } else if (EPI == 4) {
                        Chi[idx] = __float2half_rn(fmaxf(c0 * a + Fp[col], 0.0f));
                    } else if (EPI == 6) {
                        float z = a + Fp[col];
                        Cf[idx] = 1.0f / (1.0f + expf(-z));
                    } else {  // EPI 7
                        Cf[(size_t)blockIdx.z * (MPAD * MIDD) + idx] = a;
                    }
                }
            }
        }
    }
}

// ---------------------------------------------------------------------------
extern "C" void kernel_launch(void* const* d_in, const int* in_sizes, int n_in,
                              void* d_out, int out_size)
{
    const float* input_this = (const float*)d_in[0];
    const float* W_cos = (const float*)d_in[2];
    const float* W_sin = (const float*)d_in[3];
    const float* tmpl  = (const float*)d_in[4];
    const float* W1    = (const float*)d_in[5];
    const float* b1    = (const float*)d_in[6];
    const float* W2    = (const float*)d_in[7];
    const float* b2    = (const float*)d_in[8];
    const float* Wout  = (const float*)d_in[9];
    const float* bout  = (const float*)d_in[10];
    float* out = (float*)d_out;

    float *p_F, *p_Y, *p_Gf;
    cudaGetSymbolAddress((void**)&p_F,  g_F);
    cudaGetSymbolAddress((void**)&p_Y,  g_Y);
    cudaGetSymbolAddress((void**)&p_Gf, g_Gf);
    __half *p_fhi, *p_mA, *p_mB, *p_tthi, *p_G, *p_w1h, *p_w2h, *p_woh;
    cudaGetSymbolAddress((void**)&p_fhi,  g_fhi);
    cudaGetSymbolAddress((void**)&p_mA,   g_mA);
    cudaGetSymbolAddress((void**)&p_mB,   g_mB);
    cudaGetSymbolAddress((void**)&p_tthi, g_tthi);
    cudaGetSymbolAddress((void**)&p_G,    g_G);
    cudaGetSymbolAddress((void**)&p_w1h,  g_w1h);
    cudaGetSymbolAddress((void**)&p_w2h,  g_w2h);
    cudaGetSymbolAddress((void**)&p_woh,  g_woh);

    dim3 blk(256);

    splitcount_x_kernel<<<BATCH, blk>>>(input_this);
    split_w_kernel<<<(NF * LEN / 4 + 255) / 256, blk>>>(W_cos, W_sin);
    split_t_kernel<<<(NF * MIDD + 255) / 256, blk>>>(tmpl);
    conv_tailw_kernel<<<(MIDD * MIDD + PP * MIDD + PP * PP + 255) / 256, blk>>>(W1, W2, Wout);

    cudaFuncSetAttribute(fourier_hmma_kernel,
                         cudaFuncAttributeMaxDynamicSharedMemorySize, FSMEM);
    cudaFuncSetAttribute(lista_hmma_kernel<1>,
                         cudaFuncAttributeMaxDynamicSharedMemorySize, LSMEM);
    cudaFuncSetAttribute(lista_hmma_kernel<3>,
                         cudaFuncAttributeMaxDynamicSharedMemorySize, LSMEM);
    cudaFuncSetAttribute(lista_hmma_kernel<4>,
                         cudaFuncAttributeMaxDynamicSharedMemorySize, LSMEM);
    cudaFuncSetAttribute(lista_hmma_kernel<6>,
                         cudaFuncAttributeMaxDynamicSharedMemorySize, LSMEM);
    cudaFuncSetAttribute(lista_hmma_kernel<7>,
                         cudaFuncAttributeMaxDynamicSharedMemorySize, LSMEM);

    // G partials: K=2112 split 3x704 (grid.z)
    lista_hmma_kernel<7><<<dim3((MIDD + 63) / 64, MPAD / 128, 3), blk, LSMEM>>>(
        p_tthi, NF, p_tthi, NF, MIDD, NF, 704,
        nullptr, p_Gf, MIDD, nullptr, nullptr, nullptr, 0.f, 0.f);
    gconv_kernel<<<(MPAD * MIDD + 255) / 256, blk>>>();

    // Fourier (128x128 tiles, 256 threads, 2 CTA/SM — R15 config)
    fourier_hmma_kernel<<<dim3(NW / 128, BATCH / 128), blk, FSMEM>>>();

    dim3 gMID((MIDD + 63) / 64, BATCH / 128);   // 5 x 32

    // F' = 2^13 feat@T ; m0' = relu(10F)*2^13
    lista_hmma_kernel<1><<<gMID, blk, LSMEM>>>(
        p_fhi, NF, p_tthi, NF, MIDD, NF, NF,
        p_mA, p_F, MIDD, nullptr, nullptr, nullptr, 0.f, 0.f);

    // 4 fused iterations; final m' lands in g_mA
    __half* mi = p_mA;
    __half* mo = p_mB;
    for (int it = 0; it < 4; it++) {
        float c0 = (it == 0) ? -1.8f : -1.6f;
        float c1 = (it == 0) ?  0.0f :  0.2f;
        lista_hmma_kernel<3><<<gMID, blk, LSMEM>>>(
            mi, MIDD, p_G, MIDD, MIDD, MIDD, MIDD,
            mo, nullptr, MIDD, p_F, p_Y, mi, c0, c1);
        __half* tmp = mi; mi = mo; mo = tmp;
    }

    // h1 = relu(2^-13 * m'@W1^T + b1) -> g_mB (fp16)
    lista_hmma_kernel<4><<<gMID, blk, LSMEM>>>(
        p_mA, MIDD, p_w1h, MIDD, MIDD, MIDD, MIDD,
        p_mB, nullptr, MIDD, b1, nullptr, nullptr, ALPHA_INV, 0.f);

    // h2 = relu(h1@W2^T + b2) -> g_fhi reused (fp16)
    lista_hmma_kernel<4><<<dim3((PP + 63) / 64, BATCH / 128), blk, LSMEM>>>(
        p_mB, MIDD, p_w2h, MIDD, PP, MIDD, MIDD,
        p_fhi, nullptr, PP, b2, nullptr, nullptr, 1.0f, 0.f);

    // out = sigmoid(h2@Wout^T + bout) -> fp32 d_out
    lista_hmma_kernel<6><<<dim3((PP + 63) / 64, BATCH / 128), blk, LSMEM>>>(
        p_fhi, PP, p_woh, PP, PP, PP, PP,
        nullptr, out, PP, bout, nullptr, nullptr, 0.f, 0.f);
}